// round 15
// baseline (speedup 1.0000x reference)
#include <cuda_runtime.h>
#include <cuda_fp16.h>
#include <cstdint>

// Problem constants
#define BATCH 2048
#define TT    609
#define NIN   5
#define HH    8
#define D_LSTM (TT * HH)     // 4872
#define N1    4096
#define N2    1024
#define N3    609            // == TT

// Scratch (no cudaMalloc allowed) ---------------------------------------------
__device__ __half g_lstm_h[BATCH * D_LSTM];    // [2048, 4872] fp16
__device__ __half g_a1h[BATCH * N1];           // [2048, 4096] fp16
__device__ __half g_a2h[BATCH * N2];           // [2048, 1024] fp16
__device__ __half g_w1h[N1 * D_LSTM];          // fp16 W1
__device__ __half g_w2h[N2 * N1];              // fp16 W2
__device__ __half g_w3h[N3 * N2];              // fp16 W3

// ---------------------------------------------------------------------------
// weight fp32 -> fp16 conversion (once per launch)
// ---------------------------------------------------------------------------
__global__ void cvt_w_half(const float4* __restrict__ src, __half2* __restrict__ dst, int n4)
{
    int i = blockIdx.x * blockDim.x + threadIdx.x;
    if (i < n4) {
        float4 v = src[i];
        dst[2 * i + 0] = __floats2half2_rn(v.x, v.y);
        dst[2 * i + 1] = __floats2half2_rn(v.z, v.w);
    }
}

// ---------------------------------------------------------------------------
// Packed f32x2 helpers (Blackwell FFMA2 — only reachable via PTX)
// ---------------------------------------------------------------------------
__device__ __forceinline__ uint64_t pack2(float lo, float hi) {
    uint64_t r;
    asm("mov.b64 %0, {%1, %2};" : "=l"(r) : "f"(lo), "f"(hi));
    return r;
}
__device__ __forceinline__ void unpack2(uint64_t v, float& lo, float& hi) {
    asm("mov.b64 {%0, %1}, %2;" : "=f"(lo), "=f"(hi) : "l"(v));
}
__device__ __forceinline__ uint64_t ffma2(uint64_t a, uint64_t b, uint64_t c) {
    uint64_t d;
    asm("fma.rn.f32x2 %0, %1, %2, %3;" : "=l"(d) : "l"(a), "l"(b), "l"(c));
    return d;
}

__device__ __forceinline__ float tanh_hw(float x) {
    float y;
    asm("tanh.approx.f32 %0, %1;" : "=f"(y) : "f"(x));
    return y;
}

// ---------------------------------------------------------------------------
// Fused 3-layer LSTM (R13: 16 lanes/elem, layer skew, HW tanh, FFMA2)
// ---------------------------------------------------------------------------

template <int NP>
__device__ __forceinline__ void cell_p(
    const uint64_t (&wA)[NP], const uint64_t (&wB)[NP],
    const uint64_t (&uA)[4], const uint64_t (&uB)[4],
    float bA, float bB,
    const uint64_t (&in)[NP],
    uint64_t (&hp)[4],
    float& c, int half, float& hv)
{
    uint64_t pA = pack2(bA, 0.f);
    uint64_t pB = pack2(bB, 0.f);
#pragma unroll
    for (int m = 0; m < NP; m++) {
        pA = ffma2(wA[m], in[m], pA);
        pB = ffma2(wB[m], in[m], pB);
    }
#pragma unroll
    for (int m = 0; m < 4; m++) {
        pA = ffma2(uA[m], hp[m], pA);
        pB = ffma2(uB[m], hp[m], pB);
    }
    float a0, a1, b0, b1;
    unpack2(pA, a0, a1);
    unpack2(pB, b0, b1);
    float gA = a0 + a1;
    float gB = b0 + b1;

    float va = fmaf(0.5f, tanh_hw(0.5f * gA), 0.5f);
    float tb = tanh_hw(half ? 0.5f * gB : gB);
    float vb = half ? fmaf(0.5f, tb, 0.5f) : tb;

    float pa = __shfl_xor_sync(0xffffffffu, va, 8);
    float pb = __shfl_xor_sync(0xffffffffu, vb, 8);

    c = fmaf(pa, c, va * vb);
    hv = pb * tanh_hw(c);

#pragma unroll
    for (int m = 0; m < 4; m++) {
        float lo = __shfl_sync(0xffffffffu, hv, 2 * m,     16);
        float hi = __shfl_sync(0xffffffffu, hv, 2 * m + 1, 16);
        hp[m] = pack2(lo, hi);
    }
}

__global__ __launch_bounds__(32)
void lstm3_kernel(
    const float* __restrict__ x,
    const float* __restrict__ Wih1, const float* __restrict__ Whh1,
    const float* __restrict__ bih1, const float* __restrict__ bhh1,
    const float* __restrict__ Wih2, const float* __restrict__ Whh2,
    const float* __restrict__ bih2, const float* __restrict__ bhh2,
    const float* __restrict__ Wih3, const float* __restrict__ Whh3,
    const float* __restrict__ bih3, const float* __restrict__ bhh3,
    __half* __restrict__ out)
{
    const int tid  = threadIdx.x;
    const int grp  = tid >> 4;
    const int sub  = tid & 15;
    const int j    = sub & 7;
    const int half = sub >> 3;
    const int b    = blockIdx.x * 2 + grp;

    const int rowA = half * 8 + j;
    const int rowB = 16 + half * 8 + j;

    uint64_t w1A[3], w1B[3], u1A[4], u1B[4];
    {
        float wa[6] = {0.f, 0.f, 0.f, 0.f, 0.f, 0.f};
        float wb[6] = {0.f, 0.f, 0.f, 0.f, 0.f, 0.f};
#pragma unroll
        for (int i = 0; i < NIN; i++) {
            wa[i] = Wih1[rowA * NIN + i];
            wb[i] = Wih1[rowB * NIN + i];
        }
#pragma unroll
        for (int m = 0; m < 3; m++) {
            w1A[m] = pack2(wa[2 * m], wa[2 * m + 1]);
            w1B[m] = pack2(wb[2 * m], wb[2 * m + 1]);
        }
#pragma unroll
        for (int m = 0; m < 4; m++) {
            u1A[m] = pack2(Whh1[rowA * HH + 2 * m], Whh1[rowA * HH + 2 * m + 1]);
            u1B[m] = pack2(Whh1[rowB * HH + 2 * m], Whh1[rowB * HH + 2 * m + 1]);
        }
    }
    float b1A = bih1[rowA] + bhh1[rowA];
    float b1B = bih1[rowB] + bhh1[rowB];

    uint64_t w2A[4], w2B[4], u2A[4], u2B[4];
    uint64_t w3A[4], w3B[4], u3A[4], u3B[4];
#pragma unroll
    for (int m = 0; m < 4; m++) {
        w2A[m] = pack2(Wih2[rowA * HH + 2 * m], Wih2[rowA * HH + 2 * m + 1]);
        w2B[m] = pack2(Wih2[rowB * HH + 2 * m], Wih2[rowB * HH + 2 * m + 1]);
        u2A[m] = pack2(Whh2[rowA * HH + 2 * m], Whh2[rowA * HH + 2 * m + 1]);
        u2B[m] = pack2(Whh2[rowB * HH + 2 * m], Whh2[rowB * HH + 2 * m + 1]);
        w3A[m] = pack2(Wih3[rowA * HH + 2 * m], Wih3[rowA * HH + 2 * m + 1]);
        w3B[m] = pack2(Wih3[rowB * HH + 2 * m], Wih3[rowB * HH + 2 * m + 1]);
        u3A[m] = pack2(Whh3[rowA * HH + 2 * m], Whh3[rowA * HH + 2 * m + 1]);
        u3B[m] = pack2(Whh3[rowB * HH + 2 * m], Whh3[rowB * HH + 2 * m + 1]);
    }
    float b2A = bih2[rowA] + bhh2[rowA];
    float b2B = bih2[rowB] + bhh2[rowB];
    float b3A = bih3[rowA] + bhh3[rowA];
    float b3B = bih3[rowB] + bhh3[rowB];

    uint64_t hp1[4], hp2[4], hp3[4];
#pragma unroll
    for (int m = 0; m < 4; m++) {
        hp1[m] = pack2(0.f, 0.f);
        hp2[m] = pack2(0.f, 0.f);
        hp3[m] = pack2(0.f, 0.f);
    }
    float c1 = 0.f, c2 = 0.f, c3 = 0.f;

    const float* xr = x + (size_t)b * TT * NIN;
    __half* op = out + (size_t)b * D_LSTM;

    float xn[NIN];
#pragma unroll
    for (int i = 0; i < NIN; i++) xn[i] = xr[i];

    float d, hv;

    auto stepL1 = [&](const uint64_t (&xc)[3]) {
        cell_p<3>(w1A, w1B, u1A, u1B, b1A, b1B, xc, hp1, c1, half, d);
    };
    auto stepL2 = [&]() {
        cell_p<4>(w2A, w2B, u2A, u2B, b2A, b2B, hp1, hp2, c2, half, d);
    };
    auto stepL3 = [&]() {
        cell_p<4>(w3A, w3B, u3A, u3B, b3A, b3B, hp2, hp3, c3, half, hv);
    };

    auto fetch_x = [&](int tn, uint64_t (&xc)[3]) {
        xc[0] = pack2(xn[0], xn[1]);
        xc[1] = pack2(xn[2], xn[3]);
        xc[2] = pack2(xn[4], 0.f);
#pragma unroll
        for (int i = 0; i < NIN; i++) xn[i] = xr[tn * NIN + i];
    };

    {   // i = 0
        uint64_t xc[3];
        fetch_x(1, xc);
        stepL1(xc);
    }
    {   // i = 1
        uint64_t xc[3];
        fetch_x(2, xc);
        stepL2();
        stepL1(xc);
    }

    for (int i = 2; i < TT; i++) {
        uint64_t xc[3];
        const int tn = (i + 1 < TT) ? (i + 1) : (TT - 1);
        fetch_x(tn, xc);

        stepL3();
        stepL2();
        stepL1(xc);

        if (half == 0)
            op[(i - 2) * HH + j] = __float2half_rn(hv);
    }

    {
        stepL3();
        stepL2();
        if (half == 0)
            op[(TT - 2) * HH + j] = __float2half_rn(hv);
    }
    {
        stepL3();
        if (half == 0)
            op[(TT - 1) * HH + j] = __float2half_rn(hv);
    }
}

// ---------------------------------------------------------------------------
// fp16 tensor-core GEMM with ldmatrix fragment loads (R14, unchanged).
// ---------------------------------------------------------------------------

__device__ __forceinline__ void cp_async16(uint32_t dst, const void* src, int src_bytes) {
    asm volatile("cp.async.cg.shared.global [%0], [%1], 16, %2;\n"
                 :: "r"(dst), "l"(src), "r"(src_bytes));
}
__device__ __forceinline__ void cp_commit() {
    asm volatile("cp.async.commit_group;\n" ::: "memory");
}
template <int N>
__device__ __forceinline__ void cp_wait() {
    asm volatile("cp.async.wait_group %0;\n" :: "n"(N) : "memory");
}

__device__ __forceinline__ void ldsm_x4(uint32_t& r0, uint32_t& r1, uint32_t& r2,
                                        uint32_t& r3, uint32_t addr) {
    asm volatile("ldmatrix.sync.aligned.m8n8.x4.shared.b16 {%0,%1,%2,%3}, [%4];"
                 : "=r"(r0), "=r"(r1), "=r"(r2), "=r"(r3) : "r"(addr));
}

__device__ __forceinline__ void mma_f16(float (&c)[4], const uint32_t (&a)[4],
                                        const uint32_t (&b)[2]) {
    asm volatile(
        "mma.sync.aligned.m16n8k16.row.col.f32.f16.f16.f32 "
        "{%0,%1,%2,%3}, {%4,%5,%6,%7}, {%8,%9}, {%0,%1,%2,%3};"
        : "+f"(c[0]), "+f"(c[1]), "+f"(c[2]), "+f"(c[3])
        : "r"(a[0]), "r"(a[1]), "r"(a[2]), "r"(a[3]), "r"(b[0]), "r"(b[1]));
}

template <int BM, int BN, bool RELU, bool OUT_HALF>
__global__ __launch_bounds__(128, 2)
void gemm_f16(const __half* __restrict__ A, const __half* __restrict__ W,
              const float* __restrict__ bias, void* __restrict__ Cv,
              int M, int N, int K)
{
    constexpr int BK = 64;
    constexpr int THREADS = 128;
    constexpr int WARPS_M = 2, WARPS_N = 2;
    constexpr int WM = BM / WARPS_M;
    constexpr int WN = BN / WARPS_N;
    constexpr int MT = WM / 16;
    constexpr int NT = WN / 8;
    constexpr int NP = NT / 2;
    constexpr int LDW = BK / 2 + 4;

    extern __shared__ uint32_t sm[];
    uint32_t* As = sm;
    uint32_t* Bs = sm + 2 * BM * LDW;

    const int tid  = threadIdx.x;
    const int lane = tid & 31;
    const int warp = tid >> 5;
    const int wm   = warp / WARPS_N;
    const int wn   = warp % WARPS_N;
    const int g    = lane >> 2;
    const int t    = lane & 3;

    const int m0 = blockIdx.y * BM;
    const int n0 = blockIdx.x * BN;

    const uint32_t as_smem = (uint32_t)__cvta_generic_to_shared(As);
    const uint32_t bs_smem = (uint32_t)__cvta_generic_to_shared(Bs);

    uint32_t aBase[MT];
#pragma unroll
    for (int mt = 0; mt < MT; mt++) {
        const int arow = wm * WM + mt * 16 + (lane & 15);
        const int acw  = (lane >> 4) * 4;
        aBase[mt] = (uint32_t)(arow * LDW + acw) * 4u;
    }
    uint32_t bBase[NP];
#pragma unroll
    for (int p = 0; p < NP; p++) {
        const int mi  = lane >> 3;
        const int brow = wn * WN + (p * 2 + (mi >> 1)) * 8 + (lane & 7);
        const int bcw  = (mi & 1) * 4;
        bBase[p] = (uint32_t)(brow * LDW + bcw) * 4u;
    }

    float acc[MT][NT][4];
#pragma unroll
    for (int i = 0; i < MT; i++)
#pragma unroll
        for (int jj = 0; jj < NT; jj++)
#pragma unroll
            for (int q = 0; q < 4; q++) acc[i][jj][q] = 0.f;

    constexpr int KQ = BK / 8;
    constexpr int A_ITERS = BM * KQ / THREADS;
    constexpr int B_ITERS = BN * KQ / THREADS;

    auto load_tiles = [&](int k0, int stage) {
        const uint32_t a_base = as_smem + (uint32_t)stage * BM * LDW * 4;
        const uint32_t b_base = bs_smem + (uint32_t)stage * BN * LDW * 4;
#pragma unroll
        for (int r = 0; r < A_ITERS; r++) {
            const int idx = tid + r * THREADS;
            const int row = idx / KQ;
            const int kq  = idx % KQ;
            const int kg  = k0 + kq * 8;
            const bool ok = kg < K;
            const __half* src = ok ? &A[(size_t)(m0 + row) * K + kg] : A;
            cp_async16(a_base + (row * LDW + kq * 4) * 4, src, ok ? 16 : 0);
        }
#pragma unroll
        for (int r = 0; r < B_ITERS; r++) {
            const int idx = tid + r * THREADS;
            const int row = idx / KQ;
            const int kq  = idx % KQ;
            const int kg  = k0 + kq * 8;
            const bool ok = (n0 + row) < N && kg < K;
            const __half* src = ok ? &W[(size_t)(n0 + row) * K + kg] : W;
            cp_async16(b_base + (row * LDW + kq * 4) * 4, src, ok ? 16 : 0);
        }
        cp_commit();
    };

    const int nk = (K + BK - 1) / BK;

    load_tiles(0, 0);

    uint32_t af[2][MT][4], bf[2][NT][2];

    for (int it = 0; it < nk; it++) {
        const int cur = it & 1;
        if (it + 1 < nk) {
            load_tiles((it + 1) * BK, (it + 1) & 1);
            cp_wait<1>();
        } else {
            cp_wait<0>();
        }
        __syncthreads();

        const uint32_t a_cur = as_smem + (uint32_t)cur * BM * LDW * 4;
        const uint32_t b_cur = bs_smem + (uint32_t)cur * BN * LDW * 4;

        auto ldfrag = [&](int ks, int buf) {
            const uint32_t wboff = (uint32_t)(ks * 8) * 4u;
#pragma unroll
            for (int mt = 0; mt < MT; mt++)
                ldsm_x4(af[buf][mt][0], af[buf][mt][1], af[buf][mt][2], af[buf][mt][3],
                        a_cur + aBase[mt] + wboff);
#pragma unroll
            for (int p = 0; p < NP; p++)
                ldsm_x4(bf[buf][2 * p][0], bf[buf][2 * p][1],
                        bf[buf][2 * p + 1][0], bf[buf][2 * p + 1][1],
                        b_cur + bBase[p] + wboff);
        };

        ldfrag(0, 0);
#pragma unroll
        for (int ks = 0; ks < 4; ks++) {
            const int cb = ks & 1;
            if (ks + 1 < 4)
                ldfrag(ks + 1, cb ^ 1);
#pragma unroll
            for (int mt = 0; mt < MT; mt++)
#pragma unroll
                for (int nt = 0; nt < NT; nt++)
                    mma_f16(acc[mt][nt], af[cb][mt], bf[cb][nt]);
        }
        __syncthreads();
    }

#pragma unroll
    for (int mt = 0; mt < MT; mt++) {
        const int r0 = m0 + wm * WM + mt * 16 + g;
        const int r1 = r0 + 8;
#pragma unroll
        for (int nt = 0; nt < NT; nt++) {
            const int cbase = n0 + wn * WN + nt * 8 + 2 * t;
            if (OUT_HALF) {
                const float bv0 = bias[cbase], bv1 = bias[cbase + 1];
                float v00 = acc[mt][nt][0] + bv0;
                float v01 = acc[mt][nt][1] + bv1;
                float v10 = acc[mt][nt][2] + bv0;
                float v11 = acc[mt][nt][3] + bv1;
                if (RELU) {
                    v00 = fmaxf(v00, 0.f); v01 = fmaxf(v01, 0.f);
                    v10 = fmaxf(v10, 0.f); v11 = fmaxf(v11, 0.f);
                }
                __half2* C = (__half2*)Cv;
                C[((size_t)r0 * N + cbase) >> 1] = __floats2half2_rn(v00, v01);
                C[((size_t)r1 * N + cbase) >> 1] = __floats2half2_rn(v10, v11);
            } else {
                float* C = (float*)Cv;
#pragma unroll
                for (int q = 0; q < 2; q++) {
                    const int cn = cbase + q;
                    if (cn < N) {
                        const float bv = bias[cn];
                        float v0 = acc[mt][nt][q] + bv;
                        float v1 = acc[mt][nt][2 + q] + bv;
                        if (RELU) { v0 = fmaxf(v0, 0.f); v1 = fmaxf(v1, 0.f); }
                        C[(size_t)r0 * N + cn] = v0;
                        C[(size_t)r1 * N + cn] = v1;
                    }
                }
            }
        }
    }
}

// ---------------------------------------------------------------------------
// Launch: fork-join two-stream overlap.
//   stream0: LSTM_A (batch 0-1023)  -> evA ;  LSTM_B (1024-2047) -> evB
//   stream1: cvt W1/W2/W3  (overlaps LSTM_A)
//            wait evA -> GEMM1_A (rows 0-1023)   (overlaps LSTM_B)
//            wait evB -> GEMM1_B -> GEMM2 -> GEMM3 -> evJ
//   stream0: wait evJ  (join before return; graph-capture-safe fork-join)
// ---------------------------------------------------------------------------
extern "C" void kernel_launch(void* const* d_in, const int* in_sizes, int n_in,
                              void* d_out, int out_size)
{
    const float* x    = (const float*)d_in[0];
    const float* Wih1 = (const float*)d_in[1];
    const float* Whh1 = (const float*)d_in[2];
    const float* bih1 = (const float*)d_in[3];
    const float* bhh1 = (const float*)d_in[4];
    const float* Wih2 = (const float*)d_in[5];
    const float* Whh2 = (const float*)d_in[6];
    const float* bih2 = (const float*)d_in[7];
    const float* bhh2 = (const float*)d_in[8];
    const float* Wih3 = (const float*)d_in[9];
    const float* Whh3 = (const float*)d_in[10];
    const float* bih3 = (const float*)d_in[11];
    const float* bhh3 = (const float*)d_in[12];
    const float* W1   = (const float*)d_in[13];
    const float* b1   = (const float*)d_in[14];
    const float* W2   = (const float*)d_in[15];
    const float* b2   = (const float*)d_in[16];
    const float* W3   = (const float*)d_in[17];
    const float* b3   = (const float*)d_in[18];
    float* out = (float*)d_out;

    __half *lstm_h, *a1h, *a2h, *w1h, *w2h, *w3h;
    cudaGetSymbolAddress((void**)&lstm_h, g_lstm_h);
    cudaGetSymbolAddress((void**)&a1h, g_a1h);
    cudaGetSymbolAddress((void**)&a2h, g_a2h);
    cudaGetSymbolAddress((void**)&w1h, g_w1h);
    cudaGetSymbolAddress((void**)&w2h, g_w2h);
    cudaGetSymbolAddress((void**)&w3h, g_w3h);

    constexpr int LDW = 36;
    constexpr int SMEM_128 = (2 * 128 * LDW + 2 * 128 * LDW) * 4;  // 73728
    constexpr int SMEM_64  = (2 * 128 * LDW + 2 * 64 * LDW) * 4;   // 55296

    static cudaStream_t s1 = nullptr;
    static cudaEvent_t evFork = nullptr, evA = nullptr, evB = nullptr, evJ = nullptr;
    static bool init_done = false;
    if (!init_done) {
        cudaFuncSetAttribute(gemm_f16<128, 128, true, true>,
                             cudaFuncAttributeMaxDynamicSharedMemorySize, SMEM_128);
        cudaFuncSetAttribute(gemm_f16<128, 64, true, true>,
                             cudaFuncAttributeMaxDynamicSharedMemorySize, SMEM_64);
        cudaFuncSetAttribute(gemm_f16<128, 64, false, false>,
                             cudaFuncAttributeMaxDynamicSharedMemorySize, SMEM_64);
        cudaStreamCreateWithFlags(&s1, cudaStreamNonBlocking);
        cudaEventCreateWithFlags(&evFork, cudaEventDisableTiming);
        cudaEventCreateWithFlags(&evA,    cudaEventDisableTiming);
        cudaEventCreateWithFlags(&evB,    cudaEventDisableTiming);
        cudaEventCreateWithFlags(&evJ,    cudaEventDisableTiming);
        init_done = true;
    }

    const int HB = BATCH / 2;   // 1024

    // ---- fork: stream1 joins the capture via event from origin stream ----
    cudaEventRecord(evFork, 0);
    cudaStreamWaitEvent(s1, evFork, 0);

    // ---- stream1: weight conversion (independent of LSTM) ----
    {
        const int n4_1 = N1 * D_LSTM / 4;
        const int n4_2 = N2 * N1 / 4;
        const int n4_3 = N3 * N2 / 4;
        cvt_w_half<<<(n4_1 + 255) / 256, 256, 0, s1>>>((const float4*)W1, (__half2*)w1h, n4_1);
        cvt_w_half<<<(n4_2 + 255) / 256, 256, 0, s1>>>((const float4*)W2, (__half2*)w2h, n4_2);
        cvt_w_half<<<(n4_3 + 255) / 256, 256, 0, s1>>>((const float4*)W3, (__half2*)w3h, n4_3);
    }

    // ---- stream0: LSTM in two batch halves ----
    lstm3_kernel<<<HB / 2, 32>>>(x,
        Wih1, Whh1, bih1, bhh1,
        Wih2, Whh2, bih2, bhh2,
        Wih3, Whh3, bih3, bhh3,
        lstm_h);
    cudaEventRecord(evA, 0);

    lstm3_kernel<<<HB / 2, 32>>>(x + (size_t)HB * TT * NIN,
        Wih1, Whh1, bih1, bhh1,
        Wih2, Whh2, bih2, bhh2,
        Wih3, Whh3, bih3, bhh3,
        lstm_h + (size_t)HB * D_LSTM);
    cudaEventRecord(evB, 0);

    // ---- stream1: GEMM1 first half (overlaps LSTM_B) ----
    cudaStreamWaitEvent(s1, evA, 0);
    {
        dim3 grid(N1 / 128, HB / 128);
        gemm_f16<128, 128, true, true><<<grid, 128, SMEM_128, s1>>>(
            lstm_h, w1h, b1, a1h, HB, N1, D_LSTM);
    }
    // ---- stream1: GEMM1 second half, then GEMM2/GEMM3 ----
    cudaStreamWaitEvent(s1, evB, 0);
    {
        dim3 grid(N1 / 128, HB / 128);
        gemm_f16<128, 128, true, true><<<grid, 128, SMEM_128, s1>>>(
            lstm_h + (size_t)HB * D_LSTM, w1h, b1,
            a1h + (size_t)HB * N1, HB, N1, D_LSTM);
    }
    {
        dim3 grid(N2 / 64, BATCH / 128);
        gemm_f16<128, 64, true, true><<<grid, 128, SMEM_64, s1>>>(
            a1h, w2h, b2, a2h, BATCH, N2, N1);
    }
    {
        dim3 grid((N3 + 63) / 64, BATCH / 128);
        gemm_f16<128, 64, false, false><<<grid, 128, SMEM_64, s1>>>(
            a2h, w3h, b3, out, BATCH, N3, N2);
    }

    // ---- join back to origin stream ----
    cudaEventRecord(evJ, s1);
    cudaStreamWaitEvent(0, evJ, 0);
}

// round 16
// speedup vs baseline: 1.3115x; 1.3115x over previous
#include <cuda_runtime.h>
#include <cuda_fp16.h>
#include <cstdint>

// Problem constants
#define BATCH 2048
#define TT    609
#define NIN   5
#define HH    8
#define D_LSTM (TT * HH)     // 4872
#define N1    4096
#define N2    1024
#define N3    609            // == TT

// Scratch (no cudaMalloc allowed) ---------------------------------------------
__device__ __half g_lstm_h[BATCH * D_LSTM];    // [2048, 4872] fp16
__device__ __half g_a1h[BATCH * N1];           // [2048, 4096] fp16
__device__ __half g_a2h[BATCH * N2];           // [2048, 1024] fp16
__device__ __half g_w1h[N1 * D_LSTM];          // fp16 W1
__device__ __half g_w2h[N2 * N1];              // fp16 W2
__device__ __half g_w3h[N3 * N2];              // fp16 W3

// ---------------------------------------------------------------------------
// weight fp32 -> fp16 conversion (once per launch; overlapped with LSTM)
// ---------------------------------------------------------------------------
__global__ void cvt_w_half(const float4* __restrict__ src, __half2* __restrict__ dst, int n4)
{
    int i = blockIdx.x * blockDim.x + threadIdx.x;
    if (i < n4) {
        float4 v = src[i];
        dst[2 * i + 0] = __floats2half2_rn(v.x, v.y);
        dst[2 * i + 1] = __floats2half2_rn(v.z, v.w);
    }
}

// ---------------------------------------------------------------------------
// Packed f32x2 helpers (Blackwell FFMA2 — only reachable via PTX)
// ---------------------------------------------------------------------------
__device__ __forceinline__ uint64_t pack2(float lo, float hi) {
    uint64_t r;
    asm("mov.b64 %0, {%1, %2};" : "=l"(r) : "f"(lo), "f"(hi));
    return r;
}
__device__ __forceinline__ void unpack2(uint64_t v, float& lo, float& hi) {
    asm("mov.b64 {%0, %1}, %2;" : "=f"(lo), "=f"(hi) : "l"(v));
}
__device__ __forceinline__ uint64_t ffma2(uint64_t a, uint64_t b, uint64_t c) {
    uint64_t d;
    asm("fma.rn.f32x2 %0, %1, %2, %3;" : "=l"(d) : "l"(a), "l"(b), "l"(c));
    return d;
}

__device__ __forceinline__ float tanh_hw(float x) {
    float y;
    asm("tanh.approx.f32 %0, %1;" : "=f"(y) : "f"(x));
    return y;
}

// ---------------------------------------------------------------------------
// Fused 3-layer LSTM (R13/R14: 16 lanes/elem, layer skew, HW tanh, FFMA2)
// ---------------------------------------------------------------------------

template <int NP>
__device__ __forceinline__ void cell_p(
    const uint64_t (&wA)[NP], const uint64_t (&wB)[NP],
    const uint64_t (&uA)[4], const uint64_t (&uB)[4],
    float bA, float bB,
    const uint64_t (&in)[NP],
    uint64_t (&hp)[4],
    float& c, int half, float& hv)
{
    uint64_t pA = pack2(bA, 0.f);
    uint64_t pB = pack2(bB, 0.f);
#pragma unroll
    for (int m = 0; m < NP; m++) {
        pA = ffma2(wA[m], in[m], pA);
        pB = ffma2(wB[m], in[m], pB);
    }
#pragma unroll
    for (int m = 0; m < 4; m++) {
        pA = ffma2(uA[m], hp[m], pA);
        pB = ffma2(uB[m], hp[m], pB);
    }
    float a0, a1, b0, b1;
    unpack2(pA, a0, a1);
    unpack2(pB, b0, b1);
    float gA = a0 + a1;
    float gB = b0 + b1;

    float va = fmaf(0.5f, tanh_hw(0.5f * gA), 0.5f);
    float tb = tanh_hw(half ? 0.5f * gB : gB);
    float vb = half ? fmaf(0.5f, tb, 0.5f) : tb;

    float pa = __shfl_xor_sync(0xffffffffu, va, 8);
    float pb = __shfl_xor_sync(0xffffffffu, vb, 8);

    c = fmaf(pa, c, va * vb);
    hv = pb * tanh_hw(c);

#pragma unroll
    for (int m = 0; m < 4; m++) {
        float lo = __shfl_sync(0xffffffffu, hv, 2 * m,     16);
        float hi = __shfl_sync(0xffffffffu, hv, 2 * m + 1, 16);
        hp[m] = pack2(lo, hi);
    }
}

__global__ __launch_bounds__(32)
void lstm3_kernel(
    const float* __restrict__ x,
    const float* __restrict__ Wih1, const float* __restrict__ Whh1,
    const float* __restrict__ bih1, const float* __restrict__ bhh1,
    const float* __restrict__ Wih2, const float* __restrict__ Whh2,
    const float* __restrict__ bih2, const float* __restrict__ bhh2,
    const float* __restrict__ Wih3, const float* __restrict__ Whh3,
    const float* __restrict__ bih3, const float* __restrict__ bhh3,
    __half* __restrict__ out)
{
    const int tid  = threadIdx.x;
    const int grp  = tid >> 4;
    const int sub  = tid & 15;
    const int j    = sub & 7;
    const int half = sub >> 3;
    const int b    = blockIdx.x * 2 + grp;

    const int rowA = half * 8 + j;
    const int rowB = 16 + half * 8 + j;

    uint64_t w1A[3], w1B[3], u1A[4], u1B[4];
    {
        float wa[6] = {0.f, 0.f, 0.f, 0.f, 0.f, 0.f};
        float wb[6] = {0.f, 0.f, 0.f, 0.f, 0.f, 0.f};
#pragma unroll
        for (int i = 0; i < NIN; i++) {
            wa[i] = Wih1[rowA * NIN + i];
            wb[i] = Wih1[rowB * NIN + i];
        }
#pragma unroll
        for (int m = 0; m < 3; m++) {
            w1A[m] = pack2(wa[2 * m], wa[2 * m + 1]);
            w1B[m] = pack2(wb[2 * m], wb[2 * m + 1]);
        }
#pragma unroll
        for (int m = 0; m < 4; m++) {
            u1A[m] = pack2(Whh1[rowA * HH + 2 * m], Whh1[rowA * HH + 2 * m + 1]);
            u1B[m] = pack2(Whh1[rowB * HH + 2 * m], Whh1[rowB * HH + 2 * m + 1]);
        }
    }
    float b1A = bih1[rowA] + bhh1[rowA];
    float b1B = bih1[rowB] + bhh1[rowB];

    uint64_t w2A[4], w2B[4], u2A[4], u2B[4];
    uint64_t w3A[4], w3B[4], u3A[4], u3B[4];
#pragma unroll
    for (int m = 0; m < 4; m++) {
        w2A[m] = pack2(Wih2[rowA * HH + 2 * m], Wih2[rowA * HH + 2 * m + 1]);
        w2B[m] = pack2(Wih2[rowB * HH + 2 * m], Wih2[rowB * HH + 2 * m + 1]);
        u2A[m] = pack2(Whh2[rowA * HH + 2 * m], Whh2[rowA * HH + 2 * m + 1]);
        u2B[m] = pack2(Whh2[rowB * HH + 2 * m], Whh2[rowB * HH + 2 * m + 1]);
        w3A[m] = pack2(Wih3[rowA * HH + 2 * m], Wih3[rowA * HH + 2 * m + 1]);
        w3B[m] = pack2(Wih3[rowB * HH + 2 * m], Wih3[rowB * HH + 2 * m + 1]);
        u3A[m] = pack2(Whh3[rowA * HH + 2 * m], Whh3[rowA * HH + 2 * m + 1]);
        u3B[m] = pack2(Whh3[rowB * HH + 2 * m], Whh3[rowB * HH + 2 * m + 1]);
    }
    float b2A = bih2[rowA] + bhh2[rowA];
    float b2B = bih2[rowB] + bhh2[rowB];
    float b3A = bih3[rowA] + bhh3[rowA];
    float b3B = bih3[rowB] + bhh3[rowB];

    uint64_t hp1[4], hp2[4], hp3[4];
#pragma unroll
    for (int m = 0; m < 4; m++) {
        hp1[m] = pack2(0.f, 0.f);
        hp2[m] = pack2(0.f, 0.f);
        hp3[m] = pack2(0.f, 0.f);
    }
    float c1 = 0.f, c2 = 0.f, c3 = 0.f;

    const float* xr = x + (size_t)b * TT * NIN;
    __half* op = out + (size_t)b * D_LSTM;

    float xn[NIN];
#pragma unroll
    for (int i = 0; i < NIN; i++) xn[i] = xr[i];

    float d, hv;

    auto stepL1 = [&](const uint64_t (&xc)[3]) {
        cell_p<3>(w1A, w1B, u1A, u1B, b1A, b1B, xc, hp1, c1, half, d);
    };
    auto stepL2 = [&]() {
        cell_p<4>(w2A, w2B, u2A, u2B, b2A, b2B, hp1, hp2, c2, half, d);
    };
    auto stepL3 = [&]() {
        cell_p<4>(w3A, w3B, u3A, u3B, b3A, b3B, hp2, hp3, c3, half, hv);
    };

    auto fetch_x = [&](int tn, uint64_t (&xc)[3]) {
        xc[0] = pack2(xn[0], xn[1]);
        xc[1] = pack2(xn[2], xn[3]);
        xc[2] = pack2(xn[4], 0.f);
#pragma unroll
        for (int i = 0; i < NIN; i++) xn[i] = xr[tn * NIN + i];
    };

    {   // i = 0
        uint64_t xc[3];
        fetch_x(1, xc);
        stepL1(xc);
    }
    {   // i = 1
        uint64_t xc[3];
        fetch_x(2, xc);
        stepL2();
        stepL1(xc);
    }

    for (int i = 2; i < TT; i++) {
        uint64_t xc[3];
        const int tn = (i + 1 < TT) ? (i + 1) : (TT - 1);
        fetch_x(tn, xc);

        stepL3();
        stepL2();
        stepL1(xc);

        if (half == 0)
            op[(i - 2) * HH + j] = __float2half_rn(hv);
    }

    {
        stepL3();
        stepL2();
        if (half == 0)
            op[(TT - 2) * HH + j] = __float2half_rn(hv);
    }
    {
        stepL3();
        if (half == 0)
            op[(TT - 1) * HH + j] = __float2half_rn(hv);
    }
}

// ---------------------------------------------------------------------------
// fp16 tensor-core GEMM with ldmatrix fragment loads (R14, unchanged).
// ---------------------------------------------------------------------------

__device__ __forceinline__ void cp_async16(uint32_t dst, const void* src, int src_bytes) {
    asm volatile("cp.async.cg.shared.global [%0], [%1], 16, %2;\n"
                 :: "r"(dst), "l"(src), "r"(src_bytes));
}
__device__ __forceinline__ void cp_commit() {
    asm volatile("cp.async.commit_group;\n" ::: "memory");
}
template <int N>
__device__ __forceinline__ void cp_wait() {
    asm volatile("cp.async.wait_group %0;\n" :: "n"(N) : "memory");
}

__device__ __forceinline__ void ldsm_x4(uint32_t& r0, uint32_t& r1, uint32_t& r2,
                                        uint32_t& r3, uint32_t addr) {
    asm volatile("ldmatrix.sync.aligned.m8n8.x4.shared.b16 {%0,%1,%2,%3}, [%4];"
                 : "=r"(r0), "=r"(r1), "=r"(r2), "=r"(r3) : "r"(addr));
}

__device__ __forceinline__ void mma_f16(float (&c)[4], const uint32_t (&a)[4],
                                        const uint32_t (&b)[2]) {
    asm volatile(
        "mma.sync.aligned.m16n8k16.row.col.f32.f16.f16.f32 "
        "{%0,%1,%2,%3}, {%4,%5,%6,%7}, {%8,%9}, {%0,%1,%2,%3};"
        : "+f"(c[0]), "+f"(c[1]), "+f"(c[2]), "+f"(c[3])
        : "r"(a[0]), "r"(a[1]), "r"(a[2]), "r"(a[3]), "r"(b[0]), "r"(b[1]));
}

template <int BM, int BN, bool RELU, bool OUT_HALF>
__global__ __launch_bounds__(128, 2)
void gemm_f16(const __half* __restrict__ A, const __half* __restrict__ W,
              const float* __restrict__ bias, void* __restrict__ Cv,
              int M, int N, int K)
{
    constexpr int BK = 64;
    constexpr int THREADS = 128;
    constexpr int WARPS_M = 2, WARPS_N = 2;
    constexpr int WM = BM / WARPS_M;
    constexpr int WN = BN / WARPS_N;
    constexpr int MT = WM / 16;
    constexpr int NT = WN / 8;
    constexpr int NP = NT / 2;
    constexpr int LDW = BK / 2 + 4;

    extern __shared__ uint32_t sm[];
    uint32_t* As = sm;
    uint32_t* Bs = sm + 2 * BM * LDW;

    const int tid  = threadIdx.x;
    const int lane = tid & 31;
    const int warp = tid >> 5;
    const int wm   = warp / WARPS_N;
    const int wn   = warp % WARPS_N;
    const int g    = lane >> 2;
    const int t    = lane & 3;

    const int m0 = blockIdx.y * BM;
    const int n0 = blockIdx.x * BN;

    const uint32_t as_smem = (uint32_t)__cvta_generic_to_shared(As);
    const uint32_t bs_smem = (uint32_t)__cvta_generic_to_shared(Bs);

    uint32_t aBase[MT];
#pragma unroll
    for (int mt = 0; mt < MT; mt++) {
        const int arow = wm * WM + mt * 16 + (lane & 15);
        const int acw  = (lane >> 4) * 4;
        aBase[mt] = (uint32_t)(arow * LDW + acw) * 4u;
    }
    uint32_t bBase[NP];
#pragma unroll
    for (int p = 0; p < NP; p++) {
        const int mi  = lane >> 3;
        const int brow = wn * WN + (p * 2 + (mi >> 1)) * 8 + (lane & 7);
        const int bcw  = (mi & 1) * 4;
        bBase[p] = (uint32_t)(brow * LDW + bcw) * 4u;
    }

    float acc[MT][NT][4];
#pragma unroll
    for (int i = 0; i < MT; i++)
#pragma unroll
        for (int jj = 0; jj < NT; jj++)
#pragma unroll
            for (int q = 0; q < 4; q++) acc[i][jj][q] = 0.f;

    constexpr int KQ = BK / 8;
    constexpr int A_ITERS = BM * KQ / THREADS;
    constexpr int B_ITERS = BN * KQ / THREADS;

    auto load_tiles = [&](int k0, int stage) {
        const uint32_t a_base = as_smem + (uint32_t)stage * BM * LDW * 4;
        const uint32_t b_base = bs_smem + (uint32_t)stage * BN * LDW * 4;
#pragma unroll
        for (int r = 0; r < A_ITERS; r++) {
            const int idx = tid + r * THREADS;
            const int row = idx / KQ;
            const int kq  = idx % KQ;
            const int kg  = k0 + kq * 8;
            const bool ok = kg < K;
            const __half* src = ok ? &A[(size_t)(m0 + row) * K + kg] : A;
            cp_async16(a_base + (row * LDW + kq * 4) * 4, src, ok ? 16 : 0);
        }
#pragma unroll
        for (int r = 0; r < B_ITERS; r++) {
            const int idx = tid + r * THREADS;
            const int row = idx / KQ;
            const int kq  = idx % KQ;
            const int kg  = k0 + kq * 8;
            const bool ok = (n0 + row) < N && kg < K;
            const __half* src = ok ? &W[(size_t)(n0 + row) * K + kg] : W;
            cp_async16(b_base + (row * LDW + kq * 4) * 4, src, ok ? 16 : 0);
        }
        cp_commit();
    };

    const int nk = (K + BK - 1) / BK;

    load_tiles(0, 0);

    uint32_t af[2][MT][4], bf[2][NT][2];

    for (int it = 0; it < nk; it++) {
        const int cur = it & 1;
        if (it + 1 < nk) {
            load_tiles((it + 1) * BK, (it + 1) & 1);
            cp_wait<1>();
        } else {
            cp_wait<0>();
        }
        __syncthreads();

        const uint32_t a_cur = as_smem + (uint32_t)cur * BM * LDW * 4;
        const uint32_t b_cur = bs_smem + (uint32_t)cur * BN * LDW * 4;

        auto ldfrag = [&](int ks, int buf) {
            const uint32_t wboff = (uint32_t)(ks * 8) * 4u;
#pragma unroll
            for (int mt = 0; mt < MT; mt++)
                ldsm_x4(af[buf][mt][0], af[buf][mt][1], af[buf][mt][2], af[buf][mt][3],
                        a_cur + aBase[mt] + wboff);
#pragma unroll
            for (int p = 0; p < NP; p++)
                ldsm_x4(bf[buf][2 * p][0], bf[buf][2 * p][1],
                        bf[buf][2 * p + 1][0], bf[buf][2 * p + 1][1],
                        b_cur + bBase[p] + wboff);
        };

        ldfrag(0, 0);
#pragma unroll
        for (int ks = 0; ks < 4; ks++) {
            const int cb = ks & 1;
            if (ks + 1 < 4)
                ldfrag(ks + 1, cb ^ 1);
#pragma unroll
            for (int mt = 0; mt < MT; mt++)
#pragma unroll
                for (int nt = 0; nt < NT; nt++)
                    mma_f16(acc[mt][nt], af[cb][mt], bf[cb][nt]);
        }
        __syncthreads();
    }

#pragma unroll
    for (int mt = 0; mt < MT; mt++) {
        const int r0 = m0 + wm * WM + mt * 16 + g;
        const int r1 = r0 + 8;
#pragma unroll
        for (int nt = 0; nt < NT; nt++) {
            const int cbase = n0 + wn * WN + nt * 8 + 2 * t;
            if (OUT_HALF) {
                const float bv0 = bias[cbase], bv1 = bias[cbase + 1];
                float v00 = acc[mt][nt][0] + bv0;
                float v01 = acc[mt][nt][1] + bv1;
                float v10 = acc[mt][nt][2] + bv0;
                float v11 = acc[mt][nt][3] + bv1;
                if (RELU) {
                    v00 = fmaxf(v00, 0.f); v01 = fmaxf(v01, 0.f);
                    v10 = fmaxf(v10, 0.f); v11 = fmaxf(v11, 0.f);
                }
                __half2* C = (__half2*)Cv;
                C[((size_t)r0 * N + cbase) >> 1] = __floats2half2_rn(v00, v01);
                C[((size_t)r1 * N + cbase) >> 1] = __floats2half2_rn(v10, v11);
            } else {
                float* C = (float*)Cv;
#pragma unroll
                for (int q = 0; q < 2; q++) {
                    const int cn = cbase + q;
                    if (cn < N) {
                        const float bv = bias[cn];
                        float v0 = acc[mt][nt][q] + bv;
                        float v1 = acc[mt][nt][2 + q] + bv;
                        if (RELU) { v0 = fmaxf(v0, 0.f); v1 = fmaxf(v1, 0.f); }
                        C[(size_t)r0 * N + cn] = v0;
                        C[(size_t)r1 * N + cn] = v1;
                    }
                }
            }
        }
    }
}

// ---------------------------------------------------------------------------
// Launch: single full-batch LSTM (R14 structure); ONLY the weight-conversion
// kernels are forked to a second stream to overlap with the LSTM.
//   stream0: LSTM (full batch)
//   stream1: cvt W1/W2/W3 (concurrent with LSTM) -> evC
//   stream0: wait evC -> GEMM1 -> GEMM2 -> GEMM3
// ---------------------------------------------------------------------------
extern "C" void kernel_launch(void* const* d_in, const int* in_sizes, int n_in,
                              void* d_out, int out_size)
{
    const float* x    = (const float*)d_in[0];
    const float* Wih1 = (const float*)d_in[1];
    const float* Whh1 = (const float*)d_in[2];
    const float* bih1 = (const float*)d_in[3];
    const float* bhh1 = (const float*)d_in[4];
    const float* Wih2 = (const float*)d_in[5];
    const float* Whh2 = (const float*)d_in[6];
    const float* bih2 = (const float*)d_in[7];
    const float* bhh2 = (const float*)d_in[8];
    const float* Wih3 = (const float*)d_in[9];
    const float* Whh3 = (const float*)d_in[10];
    const float* bih3 = (const float*)d_in[11];
    const float* bhh3 = (const float*)d_in[12];
    const float* W1   = (const float*)d_in[13];
    const float* b1   = (const float*)d_in[14];
    const float* W2   = (const float*)d_in[15];
    const float* b2   = (const float*)d_in[16];
    const float* W3   = (const float*)d_in[17];
    const float* b3   = (const float*)d_in[18];
    float* out = (float*)d_out;

    __half *lstm_h, *a1h, *a2h, *w1h, *w2h, *w3h;
    cudaGetSymbolAddress((void**)&lstm_h, g_lstm_h);
    cudaGetSymbolAddress((void**)&a1h, g_a1h);
    cudaGetSymbolAddress((void**)&a2h, g_a2h);
    cudaGetSymbolAddress((void**)&w1h, g_w1h);
    cudaGetSymbolAddress((void**)&w2h, g_w2h);
    cudaGetSymbolAddress((void**)&w3h, g_w3h);

    constexpr int LDW = 36;
    constexpr int SMEM_128 = (2 * 128 * LDW + 2 * 128 * LDW) * 4;  // 73728
    constexpr int SMEM_64  = (2 * 128 * LDW + 2 * 64 * LDW) * 4;   // 55296

    static cudaStream_t s1 = nullptr;
    static cudaEvent_t evFork = nullptr, evC = nullptr;
    static bool init_done = false;
    if (!init_done) {
        cudaFuncSetAttribute(gemm_f16<128, 128, true, true>,
                             cudaFuncAttributeMaxDynamicSharedMemorySize, SMEM_128);
        cudaFuncSetAttribute(gemm_f16<128, 64, true, true>,
                             cudaFuncAttributeMaxDynamicSharedMemorySize, SMEM_64);
        cudaFuncSetAttribute(gemm_f16<128, 64, false, false>,
                             cudaFuncAttributeMaxDynamicSharedMemorySize, SMEM_64);
        cudaStreamCreateWithFlags(&s1, cudaStreamNonBlocking);
        cudaEventCreateWithFlags(&evFork, cudaEventDisableTiming);
        cudaEventCreateWithFlags(&evC,    cudaEventDisableTiming);
        init_done = true;
    }

    // ---- fork stream1 off the origin stream ----
    cudaEventRecord(evFork, 0);
    cudaStreamWaitEvent(s1, evFork, 0);

    // ---- stream1: weight conversion (overlaps LSTM) ----
    {
        const int n4_1 = N1 * D_LSTM / 4;
        const int n4_2 = N2 * N1 / 4;
        const int n4_3 = N3 * N2 / 4;
        cvt_w_half<<<(n4_1 + 255) / 256, 256, 0, s1>>>((const float4*)W1, (__half2*)w1h, n4_1);
        cvt_w_half<<<(n4_2 + 255) / 256, 256, 0, s1>>>((const float4*)W2, (__half2*)w2h, n4_2);
        cvt_w_half<<<(n4_3 + 255) / 256, 256, 0, s1>>>((const float4*)W3, (__half2*)w3h, n4_3);
        cudaEventRecord(evC, s1);
    }

    // ---- stream0: full-batch LSTM (1024 blocks x 32 threads) ----
    lstm3_kernel<<<BATCH / 2, 32>>>(x,
        Wih1, Whh1, bih1, bhh1,
        Wih2, Whh2, bih2, bhh2,
        Wih3, Whh3, bih3, bhh3,
        lstm_h);

    // ---- stream0: join cvt, then the GEMM chain ----
    cudaStreamWaitEvent(0, evC, 0);
    {   // [2048,4872] x [4096,4872]^T -> relu -> [2048,4096] fp16
        dim3 grid(N1 / 128, BATCH / 128);
        gemm_f16<128, 128, true, true><<<grid, 128, SMEM_128>>>(
            lstm_h, w1h, b1, a1h, BATCH, N1, D_LSTM);
    }
    {   // [2048,4096] x [1024,4096]^T -> relu -> [2048,1024] fp16
        dim3 grid(N2 / 64, BATCH / 128);
        gemm_f16<128, 64, true, true><<<grid, 128, SMEM_64>>>(
            a1h, w2h, b2, a2h, BATCH, N2, N1);
    }
    {   // [2048,1024] x [609,1024]^T -> [2048,609] fp32
        dim3 grid((N3 + 63) / 64, BATCH / 128);
        gemm_f16<128, 64, false, false><<<grid, 128, SMEM_64>>>(
            a2h, w3h, b3, out, BATCH, N3, N2);
    }
}